// round 13
// baseline (speedup 1.0000x reference)
#include <cuda_runtime.h>
#include <cstdint>

// CZ gate on qubits (i, j) of an NQUBIT-wide state, batched.
// out[b, e] = x[b, e] * (-1)^( bit_{n-1-i}(e) & bit_{n-1-j}(e) )
//
// FINAL FORM — at the measured GB300 mixed-R/W HBM ceiling:
//   256 MB irreducible traffic / ~5.9 TB/s achieved => ~36us kernel.
// Validated across MLP {1,4,8}, blocks {256,512}, ALU {10-25%}: all flat.
// Four byte-identical replays (R6/R7/R10/R11): kernel 35.5-36.7us = noise band.
//  - 4 front-batched LDG.128 per thread (MLP=4 hides DRAM latency)
//  - evict-first (.cs) loads AND stores: .wt was tested in R8 and regressed
//    9% (write-through bypasses full-line L2 writeback coalescing; L1% spiked
//    42.8->63.4 and DRAM fell to 67%). .cs is the right policy for a
//    zero-reuse stream on this part.
//  - one sign test per float4 when both wire bits are above the intra-vector
//    bits (bi,bj >= 2; true for the dataset's i=0, j=11), general fallback kept
//  - exact-division grid, no guards in the hot path

static constexpr int NQUBIT = 22;
static constexpr uint32_t DIM = 1u << NQUBIT;            // elements per batch row
static constexpr uint32_t DIM_VEC_MASK = (DIM >> 2) - 1; // float4-index mask within a row
static constexpr int THREADS = 256;
static constexpr int VPT = 4;                            // float4s per thread
static constexpr int TILE = THREADS * VPT;               // 1024 float4s per block

__device__ __forceinline__ float4 xor_sign4(float4 v, uint32_t s)
{
    v.x = __uint_as_float(__float_as_uint(v.x) ^ s);
    v.y = __uint_as_float(__float_as_uint(v.y) ^ s);
    v.z = __uint_as_float(__float_as_uint(v.z) ^ s);
    v.w = __uint_as_float(__float_as_uint(v.w) ^ s);
    return v;
}

__device__ __forceinline__ float4 apply_sign_general(float4 v, uint32_t vec_idx,
                                                     uint32_t bi, uint32_t bj)
{
    const uint32_t base = (vec_idx & DIM_VEC_MASK) << 2;
    #pragma unroll
    for (int e = 0; e < 4; e++) {
        uint32_t idx = base + (uint32_t)e;
        uint32_t s = (((idx >> bi) & (idx >> bj)) & 1u) << 31;
        reinterpret_cast<uint32_t*>(&v)[e] ^= s;
    }
    return v;
}

__global__ void __launch_bounds__(THREADS)
cz_kernel(const float4* __restrict__ x,
          const int* __restrict__ pi,
          const int* __restrict__ pj,
          float4* __restrict__ out)
{
    const int base_idx = blockIdx.x * TILE + threadIdx.x;

    const int i = __ldg(pi);
    const int j = __ldg(pj);
    const uint32_t bi = (uint32_t)(NQUBIT - 1 - i);
    const uint32_t bj = (uint32_t)(NQUBIT - 1 - j);

    // Front-batch all loads: 4 outstanding LDG.128 per thread.
    float4 v[VPT];
    #pragma unroll
    for (int k = 0; k < VPT; k++)
        v[k] = __ldcs(&x[base_idx + k * THREADS]);

    if (bi >= 2u && bj >= 2u) {
        // All 4 lanes of a float4 share the same (bi, bj) bits -> one sign per vec.
        #pragma unroll
        for (int k = 0; k < VPT; k++) {
            uint32_t e = ((uint32_t)(base_idx + k * THREADS) & DIM_VEC_MASK) << 2;
            uint32_t s = (((e >> bi) & (e >> bj)) & 1u) << 31;
            v[k] = xor_sign4(v[k], s);
        }
    } else {
        #pragma unroll
        for (int k = 0; k < VPT; k++)
            v[k] = apply_sign_general(v[k], (uint32_t)(base_idx + k * THREADS), bi, bj);
    }

    #pragma unroll
    for (int k = 0; k < VPT; k++)
        __stcs(&out[base_idx + k * THREADS], v[k]);
}

extern "C" void kernel_launch(void* const* d_in, const int* in_sizes, int n_in,
                              void* d_out, int out_size)
{
    const float4* x   = (const float4*)d_in[0];
    const int*    pi  = (const int*)d_in[1];
    const int*    pj  = (const int*)d_in[2];
    float4*       out = (float4*)d_out;

    const int n_vec = out_size / 4;          // 8 * 2^22 / 4 = 8388608 float4s
    const int blocks = n_vec / TILE;         // 8192, exact division
    cz_kernel<<<blocks, THREADS>>>(x, pi, pj, out);
}